// round 11
// baseline (speedup 1.0000x reference)
#include <cuda_runtime.h>
#include <float.h>
#include <stdint.h>

#define N_NODES 50000
#define DEG     32
#define WID     128
#define BATCH   4096
#define NT      256
#define TM      64           // k_main tile rows
#define ALD     132          // As ld (floats)
#define WLD     130          // Ws ld (uint2 units)
#define TMS     32           // k_batch / k_l2f tile rows
#define LDS2    33

// ---------------- device scratch ----------------
__device__ int   g_winner[N_NODES];
__device__ float g_Mb[BATCH * WID];
__device__ float g_Fh[BATCH * WID];
__device__ float g_H1[N_NODES * WID];
__device__ float g_M2[N_NODES * WID];
__device__ float g_A2[BATCH * WID];
__device__ float g_WaT[WID * WID];      // k-major fp32 (small kernels)
__device__ float g_WlhT[WID * WID];
__device__ float g_WlaT[WID * WID];
__device__ uint2 g_Wa2[WID * WID];      // [k][n] tf32 {hi,lo} presplit
__device__ uint2 g_Wla2[WID * WID];

typedef unsigned long long u64;

__device__ __forceinline__ u64 f2pack(float lo, float hi) {
    u64 r; asm("mov.b64 %0, {%1, %2};" : "=l"(r) : "f"(lo), "f"(hi)); return r;
}
__device__ __forceinline__ void f2unpack(u64 v, float& lo, float& hi) {
    asm("mov.b64 {%0, %1}, %2;" : "=f"(lo), "=f"(hi) : "l"(v));
}
__device__ __forceinline__ void f2fma(u64& c, u64 a, u64 b) {
    asm("fma.rn.f32x2 %0, %1, %2, %0;" : "+l"(c) : "l"(a), "l"(b));
}

// ---------------- tf32 helpers ----------------
__device__ __forceinline__ void tf32split(float f, uint32_t& hi, uint32_t& lo) {
    asm("cvt.rna.tf32.f32 %0, %1;" : "=r"(hi) : "f"(f));
    float r = f - __uint_as_float(hi);
    asm("cvt.rna.tf32.f32 %0, %1;" : "=r"(lo) : "f"(r));
}
// m16n8k8 tf32 mma. Fragment coords (lane L):
//  A (row-major 16x8): a0=(L>>2, L&3) a1=(L>>2+8, L&3) a2=(L>>2, (L&3)+4) a3=(+8,+4)
//  B (col-major 8x8):  b0=(k=L&3, n=L>>2) b1=(k=(L&3)+4, n=L>>2)
//  C (16x8): c0=(L>>2, 2*(L&3)) c1=col+1  c2=(row+8, 2*(L&3)) c3=+1
__device__ __forceinline__ void mma8(float* c, const uint32_t* a, uint32_t b0, uint32_t b1) {
    asm volatile(
        "mma.sync.aligned.m16n8k8.row.col.f32.tf32.tf32.f32 "
        "{%0,%1,%2,%3},{%4,%5,%6,%7},{%8,%9},{%0,%1,%2,%3};"
        : "+f"(c[0]), "+f"(c[1]), "+f"(c[2]), "+f"(c[3])
        : "r"(a[0]), "r"(a[1]), "r"(a[2]), "r"(a[3]), "r"(b0), "r"(b1));
}

// ---------------- small-tile GEMM (k_batch / k_l2f): 1 row/thread, LDG weights ----
__device__ __forceinline__ void gemmG1(const float* __restrict__ As,
                                       const float* __restrict__ gW,
                                       u64 C[8], int lane, int cg) {
    const float* ap = As + lane;
    const ulonglong2* bp = (const ulonglong2*)(gW + cg * 16);
#pragma unroll 4
    for (int k = 0; k < WID; ++k) {
        float a = ap[k * LDS2];
        ulonglong2 q0 = __ldg(bp + k * 32 + 0);
        ulonglong2 q1 = __ldg(bp + k * 32 + 1);
        ulonglong2 q2 = __ldg(bp + k * 32 + 2);
        ulonglong2 q3 = __ldg(bp + k * 32 + 3);
        u64 bb[8] = { q0.x, q0.y, q1.x, q1.y, q2.x, q2.y, q3.x, q3.y };
        u64 aa = f2pack(a, a);
#pragma unroll
        for (int j = 0; j < 8; ++j) f2fma(C[j], aa, bb[j]);
    }
}

__device__ __forceinline__ void unpackrow(const u64* Cr, float* v) {
#pragma unroll
    for (int j = 0; j < 8; ++j) f2unpack(Cr[j], v[2 * j], v[2 * j + 1]);
}

__device__ __forceinline__ void loadbias16(const float* __restrict__ b, int cg, float* bv) {
#pragma unroll
    for (int q = 0; q < 4; ++q) {
        float4 t = *(const float4*)(b + cg * 16 + q * 4);
        bv[q*4+0] = t.x; bv[q*4+1] = t.y; bv[q*4+2] = t.z; bv[q*4+3] = t.w;
    }
}

// ---------------- setup ----------------
__global__ void k_init(const float* __restrict__ W_agg, const float* __restrict__ W_lin) {
    int t = blockIdx.x * NT + threadIdx.x;
    if (t < N_NODES) g_winner[t] = -1;
    if (t < WID * WID) {
        int k = t >> 7, n = t & 127;            // t = k*128 + n
        float wa  = W_agg[n * WID + k];
        float wlh = W_lin[n * (2 * WID) + k];
        float wla = W_lin[n * (2 * WID) + WID + k];
        g_WaT[t]  = wa;
        g_WlhT[t] = wlh;
        g_WlaT[t] = wla;
        uint32_t hi, lo;
        tf32split(wa, hi, lo);
        g_Wa2[t] = make_uint2(hi, lo);
        tf32split(wla, hi, lo);
        g_Wla2[t] = make_uint2(hi, lo);
    }
}

__global__ void k_scatter(const int* __restrict__ node_idx) {
    int i = blockIdx.x * NT + threadIdx.x;
    if (i < BATCH) atomicMax(&g_winner[node_idx[i]], i);
}

// ---------------- batch precompute: Mb and Fh ----------------
__global__ void __launch_bounds__(NT, 3)
k_batch(const float* __restrict__ feats, const float* __restrict__ b_agg) {
    __shared__ float As[WID * LDS2];
    const int tid = threadIdx.x, lane = tid & 31, cg = tid >> 5;
    const int r0 = blockIdx.x * TMS;

    for (int e = tid; e < TMS * 32; e += NT) {
        int row = e >> 5, c4 = (e & 31) << 2;
        float4 f = *(const float4*)(feats + (r0 + row) * WID + c4);
        As[(c4 + 0) * LDS2 + row] = f.x;
        As[(c4 + 1) * LDS2 + row] = f.y;
        As[(c4 + 2) * LDS2 + row] = f.z;
        As[(c4 + 3) * LDS2 + row] = f.w;
    }
    __syncthreads();

    u64 C[8];
#pragma unroll
    for (int j = 0; j < 8; ++j) C[j] = 0ull;
    gemmG1(As, g_WaT, C, lane, cg);

    float bav[16], v[16];
    loadbias16(b_agg, cg, bav);
    unpackrow(C, v);
    float* dst = g_Mb + (r0 + lane) * WID + cg * 16;
#pragma unroll
    for (int q = 0; q < 4; ++q)
        *(float4*)(dst + q*4) = make_float4(fmaxf(v[q*4+0]+bav[q*4+0],0.f),
                                            fmaxf(v[q*4+1]+bav[q*4+1],0.f),
                                            fmaxf(v[q*4+2]+bav[q*4+2],0.f),
                                            fmaxf(v[q*4+3]+bav[q*4+3],0.f));

#pragma unroll
    for (int j = 0; j < 8; ++j) C[j] = 0ull;
    gemmG1(As, g_WlhT, C, lane, cg);
    unpackrow(C, v);
    float* dst2 = g_Fh + (r0 + lane) * WID + cg * 16;
#pragma unroll
    for (int q = 0; q < 4; ++q)
        *(float4*)(dst2 + q*4) = make_float4(v[q*4], v[q*4+1], v[q*4+2], v[q*4+3]);
}

// ---------------- tensor GEMM: 64x128x128, 3xTF32, quarter-staged B ----------------
// As: smem [row][k] fp32 ld ALD. gW: global presplit [k][n] uint2{hi,lo}.
// 8 warps: mw = warp>>1 (16 rows), nw = warp&1 (64 cols). Thread C[8 nblk][4].
__device__ __forceinline__ void tgemm(const float* __restrict__ As,
                                      const uint2* __restrict__ gW,
                                      uint2* Ws, float C[8][4],
                                      int mw, int nw, int lane) {
#pragma unroll 1
    for (int q = 0; q < 4; ++q) {
        for (int e = threadIdx.x; e < 32 * 64; e += NT) {
            int k = e >> 6, n2 = (e & 63) << 1;
            *(uint4*)(Ws + k * WLD + n2) = *(const uint4*)(gW + (q * 32 + k) * WID + n2);
        }
        __syncthreads();
#pragma unroll
        for (int ks = 0; ks < 4; ++ks) {
            int kg = q * 32 + ks * 8;
            uint32_t ahi[4], alo[4];
            const float* ap = As + (mw * 16 + (lane >> 2)) * ALD + kg + (lane & 3);
            tf32split(ap[0],           ahi[0], alo[0]);
            tf32split(ap[8 * ALD],     ahi[1], alo[1]);
            tf32split(ap[4],           ahi[2], alo[2]);
            tf32split(ap[8 * ALD + 4], ahi[3], alo[3]);
            const uint2* bp = Ws + (ks * 8 + (lane & 3)) * WLD + nw * 64 + (lane >> 2);
#pragma unroll
            for (int j = 0; j < 8; ++j) {
                uint2 b0 = bp[j * 8];
                uint2 b1 = bp[4 * WLD + j * 8];
                mma8(C[j], ahi, b0.y, b1.y);   // hi*lo
                mma8(C[j], alo, b0.x, b1.x);   // lo*hi
                mma8(C[j], ahi, b0.x, b1.x);   // hi*hi
            }
        }
        __syncthreads();
    }
}

// ---------------- main fused: layer1 (agg+combine+norm) + layer2 M2 ----------------
#define MAIN_SMEM ((TM * ALD + 32 * WLD * 2 + 2 * TM) * (int)sizeof(float))
__global__ void __launch_bounds__(NT, 3)
k_main(const int* __restrict__ nbd, const float* __restrict__ b_agg,
       const float* __restrict__ b_lin) {
    extern __shared__ float sm[];
    float* As = sm;                               // [64][132] fp32
    uint2* Ws = (uint2*)(sm + TM * ALD);          // [32][130] {hi,lo}
    float* ps = sm + TM * ALD + 32 * WLD * 2;     // [2][64]
    const int tid = threadIdx.x, lane = tid & 31, warp = tid >> 5;
    const int mw = warp >> 1, nw = warp & 1;
    const int r0 = blockIdx.x * TM;

    float cv[4];
#pragma unroll
    for (int p = 0; p < 4; ++p) cv[p] = fmaxf(b_agg[p * 32 + lane], 0.f);

    // phase A: sparse max-aggregation -> As[row][dim] (row-major, coalesced stores)
#pragma unroll 1
    for (int t = warp; t < TM; t += 8) {
        int gn = r0 + t;                          // warp-uniform
        float acc[4] = {0.f, 0.f, 0.f, 0.f};
        if (gn < N_NODES) {
            int nb = nbd[gn * DEG + lane];
            int wv = g_winner[nb];
            unsigned mask = __ballot_sync(0xffffffffu, wv >= 0);
            bool plain = (mask != 0xffffffffu);
#pragma unroll
            for (int p = 0; p < 4; ++p) acc[p] = plain ? cv[p] : -FLT_MAX;
            while (mask) {
                int j = __ffs(mask) - 1;
                mask &= mask - 1;
                int wj = __shfl_sync(0xffffffffu, wv, j);
                const float* mb = g_Mb + wj * WID + lane;
#pragma unroll
                for (int p = 0; p < 4; ++p) acc[p] = fmaxf(acc[p], mb[p * 32]);
            }
        }
#pragma unroll
        for (int p = 0; p < 4; ++p) As[t * ALD + p * 32 + lane] = acc[p];
    }
    // (first stage-sync inside tgemm orders As writes before reads)

    // GEMM 1: agg @ Wla^T
    float C[8][4];
#pragma unroll
    for (int j = 0; j < 8; ++j)
#pragma unroll
        for (int c = 0; c < 4; ++c) C[j][c] = 0.f;
    tgemm(As, g_Wla2, Ws, C, mw, nw, lane);

    // epilogue 1: + b_lin (+Fh winner), relu, row sumsq -> ps
    float2 bl[8];
#pragma unroll
    for (int j = 0; j < 8; ++j)
        bl[j] = *(const float2*)(b_lin + nw * 64 + j * 8 + 2 * (lane & 3));
    int warr[2];
#pragma unroll
    for (int h = 0; h < 2; ++h) {
        int rloc = mw * 16 + (lane >> 2) + 8 * h;
        int gn = r0 + rloc;
        int w = (gn < N_NODES) ? g_winner[gn] : -1;
        warr[h] = w;
        float s = 0.f;
#pragma unroll
        for (int j = 0; j < 8; ++j) {
            float v0 = C[j][2 * h] + bl[j].x;
            float v1 = C[j][2 * h + 1] + bl[j].y;
            if (w >= 0) {
                float2 f = *(const float2*)(g_Fh + w * WID + nw * 64 + j * 8 + 2 * (lane & 3));
                v0 += f.x; v1 += f.y;
            }
            v0 = fmaxf(v0, 0.f); v1 = fmaxf(v1, 0.f);
            s += v0 * v0 + v1 * v1;
            C[j][2 * h] = v0; C[j][2 * h + 1] = v1;
        }
        s += __shfl_xor_sync(0xffffffffu, s, 1);
        s += __shfl_xor_sync(0xffffffffu, s, 2);
        if ((lane & 3) == 0) ps[nw * TM + rloc] = s;
    }
    __syncthreads();
    // normalize, stage H1 into As, write H1 global for winner rows
#pragma unroll
    for (int h = 0; h < 2; ++h) {
        int rloc = mw * 16 + (lane >> 2) + 8 * h;
        int gn = r0 + rloc;
        float t = ps[rloc] + ps[TM + rloc];
        float rinv = 1.0f / fmaxf(sqrtf(t), 1e-12f);
        int w = warr[h];
#pragma unroll
        for (int j = 0; j < 8; ++j) {
            int col = nw * 64 + j * 8 + 2 * (lane & 3);
            float v0 = C[j][2 * h] * rinv;
            float v1 = C[j][2 * h + 1] * rinv;
            *(float2*)(As + rloc * ALD + col) = make_float2(v0, v1);
            if (w >= 0)
                *(float2*)(g_H1 + gn * WID + col) = make_float2(v0, v1);
        }
    }

    // GEMM 2: M2 = relu(H1 @ Wa^T + ba)
#pragma unroll
    for (int j = 0; j < 8; ++j)
#pragma unroll
        for (int c = 0; c < 4; ++c) C[j][c] = 0.f;
    tgemm(As, g_Wa2, Ws, C, mw, nw, lane);       // stage-sync orders As writes

    float2 ba[8];
#pragma unroll
    for (int j = 0; j < 8; ++j)
        ba[j] = *(const float2*)(b_agg + nw * 64 + j * 8 + 2 * (lane & 3));
#pragma unroll
    for (int h = 0; h < 2; ++h) {
        int rloc = mw * 16 + (lane >> 2) + 8 * h;
        int gn = r0 + rloc;
        if (gn >= N_NODES) continue;
#pragma unroll
        for (int j = 0; j < 8; ++j) {
            int col = nw * 64 + j * 8 + 2 * (lane & 3);
            float v0 = fmaxf(C[j][2 * h] + ba[j].x, 0.f);
            float v1 = fmaxf(C[j][2 * h + 1] + ba[j].y, 0.f);
            *(float2*)(g_M2 + gn * WID + col) = make_float2(v0, v1);
        }
    }
}

// ---------------- layer-2 aggregation spread across the chip ----------------
__global__ void __launch_bounds__(NT, 4)
k_agg2(const int* __restrict__ nbd, const int* __restrict__ node_idx) {
    const int lane = threadIdx.x & 31, warp = threadIdx.x >> 5;
    const int slot = blockIdx.x * 8 + warp;
    const int gn = node_idx[slot];
    int nb = nbd[gn * DEG + lane];
    float4 acc = make_float4(-FLT_MAX, -FLT_MAX, -FLT_MAX, -FLT_MAX);
#pragma unroll 1
    for (int j = 0; j < DEG; ++j) {
        int nbj = __shfl_sync(0xffffffffu, nb, j);
        float4 m = *(const float4*)(g_M2 + nbj * WID + lane * 4);
        acc.x = fmaxf(acc.x, m.x); acc.y = fmaxf(acc.y, m.y);
        acc.z = fmaxf(acc.z, m.z); acc.w = fmaxf(acc.w, m.w);
    }
    *(float4*)(g_A2 + slot * WID + lane * 4) = acc;
}

// ---------------- layer 2 final ----------------
__global__ void __launch_bounds__(NT, 2)
k_l2f(const int* __restrict__ node_idx, const float* __restrict__ b_lin,
      float* __restrict__ out) {
    __shared__ float A1[WID * LDS2];
    __shared__ float A2[WID * LDS2];
    __shared__ float ps[8 * TMS];
    __shared__ int   nid[TMS];
    const int tid = threadIdx.x, lane = tid & 31, cg = tid >> 5;
    const int r0 = blockIdx.x * TMS;

    if (tid < TMS) nid[tid] = node_idx[r0 + tid];
    __syncthreads();

    for (int e = tid; e < TMS * 32; e += NT) {
        int row = e >> 5, c4 = (e & 31) << 2;
        float4 f = *(const float4*)(g_H1 + nid[row] * WID + c4);
        A1[(c4 + 0) * LDS2 + row] = f.x;
        A1[(c4 + 1) * LDS2 + row] = f.y;
        A1[(c4 + 2) * LDS2 + row] = f.z;
        A1[(c4 + 3) * LDS2 + row] = f.w;
        float4 g = *(const float4*)(g_A2 + (r0 + row) * WID + c4);
        A2[(c4 + 0) * LDS2 + row] = g.x;
        A2[(c4 + 1) * LDS2 + row] = g.y;
        A2[(c4 + 2) * LDS2 + row] = g.z;
        A2[(c4 + 3) * LDS2 + row] = g.w;
    }
    __syncthreads();

    u64 C[8];
#pragma unroll
    for (int j = 0; j < 8; ++j) C[j] = 0ull;
    gemmG1(A1, g_WlhT, C, lane, cg);
    gemmG1(A2, g_WlaT, C, lane, cg);

    float blv[16], v[16];
    loadbias16(b_lin, cg, blv);
    unpackrow(C, v);
    float s = 0.f;
#pragma unroll
    for (int c = 0; c < 16; ++c) { v[c] = fmaxf(v[c] + blv[c], 0.f); s += v[c]*v[c]; }
    ps[cg * TMS + lane] = s;
    __syncthreads();
    float tt = 0.f;
#pragma unroll
    for (int g = 0; g < 8; ++g) tt += ps[g * TMS + lane];
    const float rinv = 1.0f / fmaxf(sqrtf(tt), 1e-12f);
    float* dst = out + (r0 + lane) * WID + cg * 16;
#pragma unroll
    for (int q = 0; q < 4; ++q)
        *(float4*)(dst + q*4) = make_float4(v[q*4]*rinv, v[q*4+1]*rinv,
                                            v[q*4+2]*rinv, v[q*4+3]*rinv);
}

// ---------------- launch ----------------
extern "C" void kernel_launch(void* const* d_in, const int* in_sizes, int n_in,
                              void* d_out, int out_size) {
    const int*   nbd      = (const int*)d_in[0];
    const int*   node_idx = (const int*)d_in[1];
    const float* feats    = (const float*)d_in[2];
    const float* W_agg    = (const float*)d_in[3];
    const float* b_agg    = (const float*)d_in[4];
    const float* W_lin    = (const float*)d_in[5];
    const float* b_lin    = (const float*)d_in[6];
    float* out = (float*)d_out;

    cudaFuncSetAttribute(k_main, cudaFuncAttributeMaxDynamicSharedMemorySize, MAIN_SMEM);

    k_init<<<(N_NODES + NT - 1) / NT, NT>>>(W_agg, W_lin);
    k_scatter<<<BATCH / NT, NT>>>(node_idx);
    k_batch<<<BATCH / TMS, NT>>>(feats, b_agg);
    k_main<<<(N_NODES + TM - 1) / TM, NT, MAIN_SMEM>>>(nbd, b_agg, b_lin);
    k_agg2<<<BATCH / 8, NT>>>(nbd, node_idx);
    k_l2f<<<BATCH / TMS, NT>>>(node_idx, b_lin, out);
}

// round 12
// speedup vs baseline: 1.1995x; 1.1995x over previous
#include <cuda_runtime.h>
#include <float.h>
#include <stdint.h>

#define N_NODES 50000
#define DEG     32
#define WID     128
#define BATCH   4096
#define NT      256
#define TM      64           // k_main tile rows
#define ALD     132          // As ld (floats)
#define WLD     130          // Ws ld (uint2 units)
#define NPAIR   64           // k-pairs per weight matrix
#define TMS     32           // k_batch / k_l2f tile rows
#define LDS2    33

// ---------------- device scratch ----------------
__device__ int   g_winner[N_NODES];
__device__ float g_Mb[BATCH * WID];
__device__ float g_Fh[BATCH * WID];
__device__ float g_H1[N_NODES * WID];
__device__ float g_M2[N_NODES * WID];
__device__ float g_A2[BATCH * WID];
__device__ float g_WaT[WID * WID];      // k-major fp32 (small kernels)
__device__ float g_WlhT[WID * WID];
__device__ float g_WlaT[WID * WID];
__device__ uint2 g_Wa2[NPAIR * WID];    // [kpair][n] bf16x2 {hi,lo}: lower16 = even k
__device__ uint2 g_Wla2[NPAIR * WID];

typedef unsigned long long u64;

__device__ __forceinline__ u64 f2pack(float lo, float hi) {
    u64 r; asm("mov.b64 %0, {%1, %2};" : "=l"(r) : "f"(lo), "f"(hi)); return r;
}
__device__ __forceinline__ void f2unpack(u64 v, float& lo, float& hi) {
    asm("mov.b64 {%0, %1}, %2;" : "=f"(lo), "=f"(hi) : "l"(v));
}
__device__ __forceinline__ void f2fma(u64& c, u64 a, u64 b) {
    asm("fma.rn.f32x2 %0, %1, %2, %0;" : "+l"(c) : "l"(a), "l"(b));
}

// ---------------- bf16 split helpers ----------------
// pack two floats (f.x -> low 16 = even k, f.y -> high 16) into bf16x2 hi + residual lo
__device__ __forceinline__ void bfsplit2(float2 f, uint32_t& hi, uint32_t& lo) {
    uint32_t h;
    asm("cvt.rn.bf16x2.f32 %0, %1, %2;" : "=r"(h) : "f"(f.y), "f"(f.x));  // d<15:0>=f.x
    float h0 = __uint_as_float(h << 16);
    float h1 = __uint_as_float(h & 0xffff0000u);
    float r0 = f.x - h0, r1 = f.y - h1;
    asm("cvt.rn.bf16x2.f32 %0, %1, %2;" : "=r"(lo) : "f"(r1), "f"(r0));
    hi = h;
}

// m16n8k16 bf16 mma. Fragment coords (lane L, g = L>>2, t = L&3):
//  A row-major 16x16: a0={row g,   k 2t,2t+1}  a1={row g+8, k 2t,2t+1}
//                     a2={row g,   k 2t+8,+9}  a3={row g+8, k 2t+8,+9}
//  B col-major 16x8:  b0={k 2t,2t+1,  col g}   b1={k 2t+8,+9, col g}
//  C 16x8 (same as m16n8k8): c0={row g, col 2t} c1=+1  c2={row g+8} c3=+1
__device__ __forceinline__ void mma16(float* c, const uint32_t* a, uint32_t b0, uint32_t b1) {
    asm volatile(
        "mma.sync.aligned.m16n8k16.row.col.f32.bf16.bf16.f32 "
        "{%0,%1,%2,%3},{%4,%5,%6,%7},{%8,%9},{%0,%1,%2,%3};"
        : "+f"(c[0]), "+f"(c[1]), "+f"(c[2]), "+f"(c[3])
        : "r"(a[0]), "r"(a[1]), "r"(a[2]), "r"(a[3]), "r"(b0), "r"(b1));
}

// ---------------- small-tile GEMM (k_batch / k_l2f): 1 row/thread, LDG weights ----
__device__ __forceinline__ void gemmG1(const float* __restrict__ As,
                                       const float* __restrict__ gW,
                                       u64 C[8], int lane, int cg) {
    const float* ap = As + lane;
    const ulonglong2* bp = (const ulonglong2*)(gW + cg * 16);
#pragma unroll 4
    for (int k = 0; k < WID; ++k) {
        float a = ap[k * LDS2];
        ulonglong2 q0 = __ldg(bp + k * 32 + 0);
        ulonglong2 q1 = __ldg(bp + k * 32 + 1);
        ulonglong2 q2 = __ldg(bp + k * 32 + 2);
        ulonglong2 q3 = __ldg(bp + k * 32 + 3);
        u64 bb[8] = { q0.x, q0.y, q1.x, q1.y, q2.x, q2.y, q3.x, q3.y };
        u64 aa = f2pack(a, a);
#pragma unroll
        for (int j = 0; j < 8; ++j) f2fma(C[j], aa, bb[j]);
    }
}

__device__ __forceinline__ void unpackrow(const u64* Cr, float* v) {
#pragma unroll
    for (int j = 0; j < 8; ++j) f2unpack(Cr[j], v[2 * j], v[2 * j + 1]);
}

__device__ __forceinline__ void loadbias16(const float* __restrict__ b, int cg, float* bv) {
#pragma unroll
    for (int q = 0; q < 4; ++q) {
        float4 t = *(const float4*)(b + cg * 16 + q * 4);
        bv[q*4+0] = t.x; bv[q*4+1] = t.y; bv[q*4+2] = t.z; bv[q*4+3] = t.w;
    }
}

// ---------------- setup ----------------
__global__ void k_init(const float* __restrict__ W_agg, const float* __restrict__ W_lin) {
    int t = blockIdx.x * NT + threadIdx.x;
    if (t < N_NODES) g_winner[t] = -1;
    if (t < WID * WID) {
        int k = t >> 7, n = t & 127;            // t = k*128 + n
        g_WaT[t]  = W_agg[n * WID + k];
        g_WlhT[t] = W_lin[n * (2 * WID) + k];
        g_WlaT[t] = W_lin[n * (2 * WID) + WID + k];
    }
    if (t < NPAIR * WID) {                      // bf16 pair presplit
        int p = t >> 7, n = t & 127;            // kpair p: k = 2p, 2p+1
        uint32_t hi, lo;
        float2 fa = make_float2(W_agg[n * WID + 2 * p], W_agg[n * WID + 2 * p + 1]);
        bfsplit2(fa, hi, lo);
        g_Wa2[t] = make_uint2(hi, lo);
        float2 fl = make_float2(W_lin[n * (2 * WID) + WID + 2 * p],
                                W_lin[n * (2 * WID) + WID + 2 * p + 1]);
        bfsplit2(fl, hi, lo);
        g_Wla2[t] = make_uint2(hi, lo);
    }
}

__global__ void k_scatter(const int* __restrict__ node_idx) {
    int i = blockIdx.x * NT + threadIdx.x;
    if (i < BATCH) atomicMax(&g_winner[node_idx[i]], i);
}

// ---------------- batch precompute: Mb and Fh ----------------
__global__ void __launch_bounds__(NT, 3)
k_batch(const float* __restrict__ feats, const float* __restrict__ b_agg) {
    __shared__ float As[WID * LDS2];
    const int tid = threadIdx.x, lane = tid & 31, cg = tid >> 5;
    const int r0 = blockIdx.x * TMS;

    for (int e = tid; e < TMS * 32; e += NT) {
        int row = e >> 5, c4 = (e & 31) << 2;
        float4 f = *(const float4*)(feats + (r0 + row) * WID + c4);
        As[(c4 + 0) * LDS2 + row] = f.x;
        As[(c4 + 1) * LDS2 + row] = f.y;
        As[(c4 + 2) * LDS2 + row] = f.z;
        As[(c4 + 3) * LDS2 + row] = f.w;
    }
    __syncthreads();

    u64 C[8];
#pragma unroll
    for (int j = 0; j < 8; ++j) C[j] = 0ull;
    gemmG1(As, g_WaT, C, lane, cg);

    float bav[16], v[16];
    loadbias16(b_agg, cg, bav);
    unpackrow(C, v);
    float* dst = g_Mb + (r0 + lane) * WID + cg * 16;
#pragma unroll
    for (int q = 0; q < 4; ++q)
        *(float4*)(dst + q*4) = make_float4(fmaxf(v[q*4+0]+bav[q*4+0],0.f),
                                            fmaxf(v[q*4+1]+bav[q*4+1],0.f),
                                            fmaxf(v[q*4+2]+bav[q*4+2],0.f),
                                            fmaxf(v[q*4+3]+bav[q*4+3],0.f));

#pragma unroll
    for (int j = 0; j < 8; ++j) C[j] = 0ull;
    gemmG1(As, g_WlhT, C, lane, cg);
    unpackrow(C, v);
    float* dst2 = g_Fh + (r0 + lane) * WID + cg * 16;
#pragma unroll
    for (int q = 0; q < 4; ++q)
        *(float4*)(dst2 + q*4) = make_float4(v[q*4], v[q*4+1], v[q*4+2], v[q*4+3]);
}

// ---------------- tensor GEMM: 64x128x128, 3-term bf16 k16, half-staged B ----------------
// As: smem [row][k] fp32 ld ALD. gW: global presplit [kpair][n] uint2{hi,lo}.
// 8 warps: mw = warp>>1 (16 rows), nw = warp&1 (64 cols). Thread C[8 nblk][4].
__device__ __forceinline__ void tgemm(const float* __restrict__ As,
                                      const uint2* __restrict__ gW,
                                      uint2* Ws, float C[8][4],
                                      int mw, int nw, int lane) {
    const int g = lane >> 2, t = lane & 3;
#pragma unroll 1
    for (int q = 0; q < 2; ++q) {               // two 64-k stages (32 pairs each)
        for (int e = threadIdx.x; e < 32 * 64; e += NT) {
            int p = e >> 6, n2 = (e & 63) << 1;
            *(uint4*)(Ws + p * WLD + n2) = *(const uint4*)(gW + (q * 32 + p) * WID + n2);
        }
        __syncthreads();
#pragma unroll
        for (int ks = 0; ks < 4; ++ks) {        // 4 x k16 per stage
            int kg = q * 64 + ks * 16;
            const float* ap0 = As + (mw * 16 + g) * ALD + kg + 2 * t;
            const float* ap1 = ap0 + 8 * ALD;
            uint32_t ahi[4], alo[4];
            bfsplit2(*(const float2*)(ap0),     ahi[0], alo[0]);
            bfsplit2(*(const float2*)(ap1),     ahi[1], alo[1]);
            bfsplit2(*(const float2*)(ap0 + 8), ahi[2], alo[2]);
            bfsplit2(*(const float2*)(ap1 + 8), ahi[3], alo[3]);
            const uint2* bp0 = Ws + (ks * 8 + t) * WLD + nw * 64 + g;
            const uint2* bp1 = bp0 + 4 * WLD;
#pragma unroll
            for (int j = 0; j < 8; ++j) {
                uint2 b0 = bp0[j * 8];
                uint2 b1 = bp1[j * 8];
                mma16(C[j], ahi, b0.y, b1.y);   // hi * lo
                mma16(C[j], alo, b0.x, b1.x);   // lo * hi
                mma16(C[j], ahi, b0.x, b1.x);   // hi * hi
            }
        }
        __syncthreads();
    }
}

// ---------------- main fused: layer1 (agg+combine+norm) + layer2 M2 ----------------
#define MAIN_SMEM ((TM * ALD + 32 * WLD * 2 + 2 * TM) * (int)sizeof(float))
__global__ void __launch_bounds__(NT, 3)
k_main(const int* __restrict__ nbd, const float* __restrict__ b_agg,
       const float* __restrict__ b_lin) {
    extern __shared__ float sm[];
    float* As = sm;                               // [64][132] fp32
    uint2* Ws = (uint2*)(sm + TM * ALD);          // [32 pairs][130] {hi,lo}
    float* ps = sm + TM * ALD + 32 * WLD * 2;     // [2][64]
    const int tid = threadIdx.x, lane = tid & 31, warp = tid >> 5;
    const int mw = warp >> 1, nw = warp & 1;
    const int r0 = blockIdx.x * TM;

    float cv[4];
#pragma unroll
    for (int p = 0; p < 4; ++p) cv[p] = fmaxf(b_agg[p * 32 + lane], 0.f);

    // phase A: sparse max-aggregation -> As[row][dim]
#pragma unroll 1
    for (int t = warp; t < TM; t += 8) {
        int gn = r0 + t;                          // warp-uniform
        float acc[4] = {0.f, 0.f, 0.f, 0.f};
        if (gn < N_NODES) {
            int nb = nbd[gn * DEG + lane];
            int wv = g_winner[nb];
            unsigned mask = __ballot_sync(0xffffffffu, wv >= 0);
            bool plain = (mask != 0xffffffffu);
#pragma unroll
            for (int p = 0; p < 4; ++p) acc[p] = plain ? cv[p] : -FLT_MAX;
            while (mask) {
                int j = __ffs(mask) - 1;
                mask &= mask - 1;
                int wj = __shfl_sync(0xffffffffu, wv, j);
                const float* mb = g_Mb + wj * WID + lane;
#pragma unroll
                for (int p = 0; p < 4; ++p) acc[p] = fmaxf(acc[p], mb[p * 32]);
            }
        }
#pragma unroll
        for (int p = 0; p < 4; ++p) As[t * ALD + p * 32 + lane] = acc[p];
    }
    // (first stage-sync inside tgemm orders As writes before reads)

    // GEMM 1: agg @ Wla^T
    float C[8][4];
#pragma unroll
    for (int j = 0; j < 8; ++j)
#pragma unroll
        for (int c = 0; c < 4; ++c) C[j][c] = 0.f;
    tgemm(As, g_Wla2, Ws, C, mw, nw, lane);

    // epilogue 1: + b_lin (+Fh winner), relu, row sumsq -> ps
    float2 bl[8];
#pragma unroll
    for (int j = 0; j < 8; ++j)
        bl[j] = *(const float2*)(b_lin + nw * 64 + j * 8 + 2 * (lane & 3));
    int warr[2];
#pragma unroll
    for (int h = 0; h < 2; ++h) {
        int rloc = mw * 16 + (lane >> 2) + 8 * h;
        int gn = r0 + rloc;
        int w = (gn < N_NODES) ? g_winner[gn] : -1;
        warr[h] = w;
        float s = 0.f;
#pragma unroll
        for (int j = 0; j < 8; ++j) {
            float v0 = C[j][2 * h] + bl[j].x;
            float v1 = C[j][2 * h + 1] + bl[j].y;
            if (w >= 0) {
                float2 f = *(const float2*)(g_Fh + w * WID + nw * 64 + j * 8 + 2 * (lane & 3));
                v0 += f.x; v1 += f.y;
            }
            v0 = fmaxf(v0, 0.f); v1 = fmaxf(v1, 0.f);
            s += v0 * v0 + v1 * v1;
            C[j][2 * h] = v0; C[j][2 * h + 1] = v1;
        }
        s += __shfl_xor_sync(0xffffffffu, s, 1);
        s += __shfl_xor_sync(0xffffffffu, s, 2);
        if ((lane & 3) == 0) ps[nw * TM + rloc] = s;
    }
    __syncthreads();
    // normalize, stage H1 into As, write H1 global for winner rows
#pragma unroll
    for (int h = 0; h < 2; ++h) {
        int rloc = mw * 16 + (lane >> 2) + 8 * h;
        int gn = r0 + rloc;
        float t = ps[rloc] + ps[TM + rloc];
        float rinv = 1.0f / fmaxf(sqrtf(t), 1e-12f);
        int w = warr[h];
#pragma unroll
        for (int j = 0; j < 8; ++j) {
            int col = nw * 64 + j * 8 + 2 * (lane & 3);
            float v0 = C[j][2 * h] * rinv;
            float v1 = C[j][2 * h + 1] * rinv;
            *(float2*)(As + rloc * ALD + col) = make_float2(v0, v1);
            if (w >= 0)
                *(float2*)(g_H1 + gn * WID + col) = make_float2(v0, v1);
        }
    }

    // GEMM 2: M2 = relu(H1 @ Wa^T + ba)
#pragma unroll
    for (int j = 0; j < 8; ++j)
#pragma unroll
        for (int c = 0; c < 4; ++c) C[j][c] = 0.f;
    tgemm(As, g_Wa2, Ws, C, mw, nw, lane);       // stage-sync orders As writes

    float2 ba[8];
#pragma unroll
    for (int j = 0; j < 8; ++j)
        ba[j] = *(const float2*)(b_agg + nw * 64 + j * 8 + 2 * (lane & 3));
#pragma unroll
    for (int h = 0; h < 2; ++h) {
        int rloc = mw * 16 + (lane >> 2) + 8 * h;
        int gn = r0 + rloc;
        if (gn >= N_NODES) continue;
#pragma unroll
        for (int j = 0; j < 8; ++j) {
            int col = nw * 64 + j * 8 + 2 * (lane & 3);
            float v0 = fmaxf(C[j][2 * h] + ba[j].x, 0.f);
            float v1 = fmaxf(C[j][2 * h + 1] + ba[j].y, 0.f);
            *(float2*)(g_M2 + gn * WID + col) = make_float2(v0, v1);
        }
    }
}

// ---------------- layer-2 aggregation spread across the chip ----------------
__global__ void __launch_bounds__(NT, 4)
k_agg2(const int* __restrict__ nbd, const int* __restrict__ node_idx) {
    const int lane = threadIdx.x & 31, warp = threadIdx.x >> 5;
    const int slot = blockIdx.x * 8 + warp;
    const int gn = node_idx[slot];
    int nb = nbd[gn * DEG + lane];
    float4 acc = make_float4(-FLT_MAX, -FLT_MAX, -FLT_MAX, -FLT_MAX);
#pragma unroll 1
    for (int j = 0; j < DEG; ++j) {
        int nbj = __shfl_sync(0xffffffffu, nb, j);
        float4 m = *(const float4*)(g_M2 + nbj * WID + lane * 4);
        acc.x = fmaxf(acc.x, m.x); acc.y = fmaxf(acc.y, m.y);
        acc.z = fmaxf(acc.z, m.z); acc.w = fmaxf(acc.w, m.w);
    }
    *(float4*)(g_A2 + slot * WID + lane * 4) = acc;
}

// ---------------- layer 2 final ----------------
__global__ void __launch_bounds__(NT, 2)
k_l2f(const int* __restrict__ node_idx, const float* __restrict__ b_lin,
      float* __restrict__ out) {
    __shared__ float A1[WID * LDS2];
    __shared__ float A2[WID * LDS2];
    __shared__ float ps[8 * TMS];
    __shared__ int   nid[TMS];
    const int tid = threadIdx.x, lane = tid & 31, cg = tid >> 5;
    const int r0 = blockIdx.x * TMS;

    if (tid < TMS) nid[tid] = node_idx[r0 + tid];
    __syncthreads();

    for (int e = tid; e < TMS * 32; e += NT) {
        int row = e >> 5, c4 = (e & 31) << 2;
        float4 f = *(const float4*)(g_H1 + nid[row] * WID + c4);
        A1[(c4 + 0) * LDS2 + row] = f.x;
        A1[(c4 + 1) * LDS2 + row] = f.y;
        A1[(c4 + 2) * LDS2 + row] = f.z;
        A1[(c4 + 3) * LDS2 + row] = f.w;
        float4 g = *(const float4*)(g_A2 + (r0 + row) * WID + c4);
        A2[(c4 + 0) * LDS2 + row] = g.x;
        A2[(c4 + 1) * LDS2 + row] = g.y;
        A2[(c4 + 2) * LDS2 + row] = g.z;
        A2[(c4 + 3) * LDS2 + row] = g.w;
    }
    __syncthreads();

    u64 C[8];
#pragma unroll
    for (int j = 0; j < 8; ++j) C[j] = 0ull;
    gemmG1(A1, g_WlhT, C, lane, cg);
    gemmG1(A2, g_WlaT, C, lane, cg);

    float blv[16], v[16];
    loadbias16(b_lin, cg, blv);
    unpackrow(C, v);
    float s = 0.f;
#pragma unroll
    for (int c = 0; c < 16; ++c) { v[c] = fmaxf(v[c] + blv[c], 0.f); s += v[c]*v[c]; }
    ps[cg * TMS + lane] = s;
    __syncthreads();
    float tt = 0.f;
#pragma unroll
    for (int g = 0; g < 8; ++g) tt += ps[g * TMS + lane];
    const float rinv = 1.0f / fmaxf(sqrtf(tt), 1e-12f);
    float* dst = out + (r0 + lane) * WID + cg * 16;
#pragma unroll
    for (int q = 0; q < 4; ++q)
        *(float4*)(dst + q*4) = make_float4(v[q*4]*rinv, v[q*4+1]*rinv,
                                            v[q*4+2]*rinv, v[q*4+3]*rinv);
}

// ---------------- launch ----------------
extern "C" void kernel_launch(void* const* d_in, const int* in_sizes, int n_in,
                              void* d_out, int out_size) {
    const int*   nbd      = (const int*)d_in[0];
    const int*   node_idx = (const int*)d_in[1];
    const float* feats    = (const float*)d_in[2];
    const float* W_agg    = (const float*)d_in[3];
    const float* b_agg    = (const float*)d_in[4];
    const float* W_lin    = (const float*)d_in[5];
    const float* b_lin    = (const float*)d_in[6];
    float* out = (float*)d_out;

    cudaFuncSetAttribute(k_main, cudaFuncAttributeMaxDynamicSharedMemorySize, MAIN_SMEM);

    k_init<<<(N_NODES + NT - 1) / NT, NT>>>(W_agg, W_lin);
    k_scatter<<<BATCH / NT, NT>>>(node_idx);
    k_batch<<<BATCH / TMS, NT>>>(feats, b_agg);
    k_main<<<(N_NODES + TM - 1) / TM, NT, MAIN_SMEM>>>(nbd, b_agg, b_lin);
    k_agg2<<<BATCH / 8, NT>>>(nbd, node_idx);
    k_l2f<<<BATCH / TMS, NT>>>(node_idx, b_lin, out);
}

// round 13
// speedup vs baseline: 1.4629x; 1.2197x over previous
#include <cuda_runtime.h>
#include <float.h>
#include <stdint.h>

#define N_NODES 50000
#define DEG     32
#define WID     128
#define BATCH   4096
#define NT      256
#define TM      64           // tile rows (all tensor kernels)
#define APLD    66           // A-pair ld (uint2 units)
#define WLD     130          // Ws ld (uint2 units)
#define NPAIR   64           // k-pairs per weight matrix

// ---------------- device scratch ----------------
__device__ int   g_winner[N_NODES];
__device__ float g_Mb[BATCH * WID];
__device__ float g_Fh[BATCH * WID];
__device__ float g_H1[N_NODES * WID];
__device__ float g_M2[N_NODES * WID];
__device__ float g_A2[BATCH * WID];
__device__ uint2 g_Wa2[NPAIR * WID];    // [kpair][n] bf16x2 {hi,lo}: low16 = even k
__device__ uint2 g_Wla2[NPAIR * WID];
__device__ uint2 g_Wlh2[NPAIR * WID];

// ---------------- bf16 split helpers ----------------
// pack two floats (f.x -> low 16 = even k, f.y -> high 16) into bf16x2 hi + residual lo
__device__ __forceinline__ void bfsplit2(float2 f, uint32_t& hi, uint32_t& lo) {
    uint32_t h;
    asm("cvt.rn.bf16x2.f32 %0, %1, %2;" : "=r"(h) : "f"(f.y), "f"(f.x));  // d<15:0>=f.x
    float h0 = __uint_as_float(h << 16);
    float h1 = __uint_as_float(h & 0xffff0000u);
    float r0 = f.x - h0, r1 = f.y - h1;
    asm("cvt.rn.bf16x2.f32 %0, %1, %2;" : "=r"(lo) : "f"(r1), "f"(r0));
    hi = h;
}

// m16n8k16 bf16 mma (fragment coords as validated in R12).
__device__ __forceinline__ void mma16(float* c, const uint32_t* a, uint32_t b0, uint32_t b1) {
    asm volatile(
        "mma.sync.aligned.m16n8k16.row.col.f32.bf16.bf16.f32 "
        "{%0,%1,%2,%3},{%4,%5,%6,%7},{%8,%9},{%0,%1,%2,%3};"
        : "+f"(c[0]), "+f"(c[1]), "+f"(c[2]), "+f"(c[3])
        : "r"(a[0]), "r"(a[1]), "r"(a[2]), "r"(a[3]), "r"(b0), "r"(b1));
}

__device__ __forceinline__ void zeroC(float C[8][4]) {
#pragma unroll
    for (int j = 0; j < 8; ++j)
#pragma unroll
        for (int c = 0; c < 4; ++c) C[j][c] = 0.f;
}

// ---------------- shared tensor GEMM: 64x128x128, A pre-split in smem ----------------
// Apk: smem [row][kpair] uint2{hi,lo}, ld APLD. gW: global presplit [kpair][n].
// 8 warps: mw = warp>>1 (16 rows), nw = warp&1 (64 cols). C[8 nblk][4]. Accumulates.
__device__ __forceinline__ void tgemm(const uint2* __restrict__ Apk,
                                      const uint2* __restrict__ gW,
                                      uint2* Ws, float C[8][4],
                                      int mw, int nw, int lane) {
    const int g = lane >> 2, t = lane & 3;
#pragma unroll 1
    for (int q = 0; q < 2; ++q) {               // two 64-k stages (32 pairs each)
        for (int e = threadIdx.x; e < 32 * 64; e += NT) {
            int p = e >> 6, n2 = (e & 63) << 1;
            *(uint4*)(Ws + p * WLD + n2) = *(const uint4*)(gW + (q * 32 + p) * WID + n2);
        }
        __syncthreads();
#pragma unroll
        for (int ks = 0; ks < 4; ++ks) {        // 4 x k16 per stage
            int pk = q * 32 + ks * 8;
            const uint2* ap0 = Apk + (mw * 16 + g) * APLD + pk + t;
            const uint2* ap1 = ap0 + 8 * APLD;
            uint2 p0 = ap0[0], p1 = ap1[0], p2 = ap0[4], p3 = ap1[4];
            uint32_t ahi[4] = { p0.x, p1.x, p2.x, p3.x };
            uint32_t alo[4] = { p0.y, p1.y, p2.y, p3.y };
            const uint2* bp0 = Ws + (ks * 8 + t) * WLD + nw * 64 + g;
            const uint2* bp1 = bp0 + 4 * WLD;
#pragma unroll
            for (int j = 0; j < 8; ++j) {
                uint2 b0 = bp0[j * 8];
                uint2 b1 = bp1[j * 8];
                mma16(C[j], ahi, b0.y, b1.y);   // hi * lo
                mma16(C[j], alo, b0.x, b1.x);   // lo * hi
                mma16(C[j], ahi, b0.x, b1.x);   // hi * hi
            }
        }
        __syncthreads();
    }
}

// ---------------- setup ----------------
__global__ void k_init(const float* __restrict__ W_agg, const float* __restrict__ W_lin) {
    int t = blockIdx.x * NT + threadIdx.x;
    if (t < N_NODES) g_winner[t] = -1;
    if (t < NPAIR * WID) {                      // bf16 pair presplit, kpair p: k = 2p, 2p+1
        int p = t >> 7, n = t & 127;
        uint32_t hi, lo;
        float2 fa = make_float2(W_agg[n * WID + 2 * p], W_agg[n * WID + 2 * p + 1]);
        bfsplit2(fa, hi, lo);
        g_Wa2[t] = make_uint2(hi, lo);
        float2 fh = make_float2(W_lin[n * (2 * WID) + 2 * p],
                                W_lin[n * (2 * WID) + 2 * p + 1]);
        bfsplit2(fh, hi, lo);
        g_Wlh2[t] = make_uint2(hi, lo);
        float2 fl = make_float2(W_lin[n * (2 * WID) + WID + 2 * p],
                                W_lin[n * (2 * WID) + WID + 2 * p + 1]);
        bfsplit2(fl, hi, lo);
        g_Wla2[t] = make_uint2(hi, lo);
    }
}

__global__ void k_scatter(const int* __restrict__ node_idx) {
    int i = blockIdx.x * NT + threadIdx.x;
    if (i < BATCH) atomicMax(&g_winner[node_idx[i]], i);
}

// ---------------- batch precompute: Mb and Fh (tensor path) ----------------
#define BATCH_SMEM ((TM * APLD + 32 * WLD) * 8)
__global__ void __launch_bounds__(NT, 2)
k_batch(const float* __restrict__ feats, const float* __restrict__ b_agg) {
    extern __shared__ float sm[];
    uint2* Apk = (uint2*)sm;
    uint2* Ws  = Apk + TM * APLD;
    const int tid = threadIdx.x, lane = tid & 31, warp = tid >> 5;
    const int mw = warp >> 1, nw = warp & 1;
    const int g = lane >> 2, t4 = lane & 3;
    const int r0 = blockIdx.x * TM;

    // stage feats split into pairs
    for (int e = tid; e < TM * 64; e += NT) {
        int row = e >> 6, p = e & 63;
        float2 f = *(const float2*)(feats + (r0 + row) * WID + 2 * p);
        uint32_t hi, lo;
        bfsplit2(f, hi, lo);
        Apk[row * APLD + p] = make_uint2(hi, lo);
    }
    // (tgemm's first stage-sync orders Apk writes before reads)

    float C[8][4];
    zeroC(C);
    tgemm(Apk, g_Wa2, Ws, C, mw, nw, lane);

    float2 ba[8];
#pragma unroll
    for (int j = 0; j < 8; ++j)
        ba[j] = *(const float2*)(b_agg + nw * 64 + j * 8 + 2 * t4);
#pragma unroll
    for (int h = 0; h < 2; ++h) {
        int row = r0 + mw * 16 + g + 8 * h;
#pragma unroll
        for (int j = 0; j < 8; ++j) {
            float v0 = fmaxf(C[j][2 * h] + ba[j].x, 0.f);
            float v1 = fmaxf(C[j][2 * h + 1] + ba[j].y, 0.f);
            *(float2*)(g_Mb + row * WID + nw * 64 + j * 8 + 2 * t4) = make_float2(v0, v1);
        }
    }

    zeroC(C);
    tgemm(Apk, g_Wlh2, Ws, C, mw, nw, lane);
#pragma unroll
    for (int h = 0; h < 2; ++h) {
        int row = r0 + mw * 16 + g + 8 * h;
#pragma unroll
        for (int j = 0; j < 8; ++j)
            *(float2*)(g_Fh + row * WID + nw * 64 + j * 8 + 2 * t4) =
                make_float2(C[j][2 * h], C[j][2 * h + 1]);
    }
}

// ---------------- main fused: layer1 (agg+combine+norm) + layer2 M2 ----------------
#define MAIN_SMEM ((TM * APLD + 32 * WLD) * 8 + 2 * TM * 4)
__global__ void __launch_bounds__(NT, 3)
k_main(const int* __restrict__ nbd, const float* __restrict__ b_agg,
       const float* __restrict__ b_lin) {
    extern __shared__ float sm[];
    uint2* Apk = (uint2*)sm;                      // [64][66] {hi,lo} pairs
    uint2* Ws  = Apk + TM * APLD;                 // [32 pairs][130]
    float* ps  = (float*)(Ws + 32 * WLD);         // [2][64]
    const int tid = threadIdx.x, lane = tid & 31, warp = tid >> 5;
    const int mw = warp >> 1, nw = warp & 1;
    const int g = lane >> 2, t4 = lane & 3;
    const int r0 = blockIdx.x * TM;

    // cvec pairs: lane owns dim pairs (2*lane, 2*lane+1) and (64+2*lane, +1)
    float2 bg0 = *(const float2*)(b_agg + 2 * lane);
    float2 bg1 = *(const float2*)(b_agg + 64 + 2 * lane);
    float2 cv0 = make_float2(fmaxf(bg0.x, 0.f), fmaxf(bg0.y, 0.f));
    float2 cv1 = make_float2(fmaxf(bg1.x, 0.f), fmaxf(bg1.y, 0.f));

    // phase A: sparse max-aggregation -> split directly into Apk
#pragma unroll 1
    for (int t = warp; t < TM; t += 8) {
        int gn = r0 + t;                          // warp-uniform
        float2 a0 = make_float2(0.f, 0.f), a1 = make_float2(0.f, 0.f);
        if (gn < N_NODES) {
            int nb = nbd[gn * DEG + lane];
            int wv = g_winner[nb];
            unsigned mask = __ballot_sync(0xffffffffu, wv >= 0);
            bool plain = (mask != 0xffffffffu);
            a0 = plain ? cv0 : make_float2(-FLT_MAX, -FLT_MAX);
            a1 = plain ? cv1 : make_float2(-FLT_MAX, -FLT_MAX);
            while (mask) {
                int j = __ffs(mask) - 1;
                mask &= mask - 1;
                int wj = __shfl_sync(0xffffffffu, wv, j);
                const float* mb = g_Mb + wj * WID;
                float2 m0 = *(const float2*)(mb + 2 * lane);
                float2 m1 = *(const float2*)(mb + 64 + 2 * lane);
                a0.x = fmaxf(a0.x, m0.x); a0.y = fmaxf(a0.y, m0.y);
                a1.x = fmaxf(a1.x, m1.x); a1.y = fmaxf(a1.y, m1.y);
            }
        }
        uint32_t hi, lo;
        bfsplit2(a0, hi, lo);
        Apk[t * APLD + lane] = make_uint2(hi, lo);
        bfsplit2(a1, hi, lo);
        Apk[t * APLD + 32 + lane] = make_uint2(hi, lo);
    }
    // (tgemm's first stage-sync orders Apk writes before reads)

    // GEMM 1: agg @ Wla^T
    float C[8][4];
    zeroC(C);
    tgemm(Apk, g_Wla2, Ws, C, mw, nw, lane);

    // epilogue 1: + b_lin (+Fh winner), relu, row sumsq -> ps
    float2 bl[8];
#pragma unroll
    for (int j = 0; j < 8; ++j)
        bl[j] = *(const float2*)(b_lin + nw * 64 + j * 8 + 2 * t4);
    int warr[2];
#pragma unroll
    for (int h = 0; h < 2; ++h) {
        int rloc = mw * 16 + g + 8 * h;
        int gn = r0 + rloc;
        int w = (gn < N_NODES) ? g_winner[gn] : -1;
        warr[h] = w;
        float s = 0.f;
#pragma unroll
        for (int j = 0; j < 8; ++j) {
            float v0 = C[j][2 * h] + bl[j].x;
            float v1 = C[j][2 * h + 1] + bl[j].y;
            if (w >= 0) {
                float2 f = *(const float2*)(g_Fh + w * WID + nw * 64 + j * 8 + 2 * t4);
                v0 += f.x; v1 += f.y;
            }
            v0 = fmaxf(v0, 0.f); v1 = fmaxf(v1, 0.f);
            s += v0 * v0 + v1 * v1;
            C[j][2 * h] = v0; C[j][2 * h + 1] = v1;
        }
        s += __shfl_xor_sync(0xffffffffu, s, 1);
        s += __shfl_xor_sync(0xffffffffu, s, 2);
        if (t4 == 0) ps[nw * TM + rloc] = s;
    }
    __syncthreads();
    // normalize, stage H1 pairs into Apk, write H1 global for winner rows
#pragma unroll
    for (int h = 0; h < 2; ++h) {
        int rloc = mw * 16 + g + 8 * h;
        int gn = r0 + rloc;
        float t = ps[rloc] + ps[TM + rloc];
        float rinv = 1.0f / fmaxf(sqrtf(t), 1e-12f);
        int w = warr[h];
#pragma unroll
        for (int j = 0; j < 8; ++j) {
            float v0 = C[j][2 * h] * rinv;
            float v1 = C[j][2 * h + 1] * rinv;
            uint32_t hi, lo;
            bfsplit2(make_float2(v0, v1), hi, lo);
            Apk[rloc * APLD + nw * 32 + j * 4 + t4] = make_uint2(hi, lo);
            if (w >= 0)
                *(float2*)(g_H1 + gn * WID + nw * 64 + j * 8 + 2 * t4) = make_float2(v0, v1);
        }
    }

    // GEMM 2: M2 = relu(H1 @ Wa^T + ba)
    zeroC(C);
    tgemm(Apk, g_Wa2, Ws, C, mw, nw, lane);      // stage-sync orders Apk writes

    float2 ba[8];
#pragma unroll
    for (int j = 0; j < 8; ++j)
        ba[j] = *(const float2*)(b_agg + nw * 64 + j * 8 + 2 * t4);
#pragma unroll
    for (int h = 0; h < 2; ++h) {
        int rloc = mw * 16 + g + 8 * h;
        int gn = r0 + rloc;
        if (gn >= N_NODES) continue;
#pragma unroll
        for (int j = 0; j < 8; ++j) {
            float v0 = fmaxf(C[j][2 * h] + ba[j].x, 0.f);
            float v1 = fmaxf(C[j][2 * h + 1] + ba[j].y, 0.f);
            *(float2*)(g_M2 + gn * WID + nw * 64 + j * 8 + 2 * t4) = make_float2(v0, v1);
        }
    }
}

// ---------------- layer-2 aggregation spread across the chip ----------------
__global__ void __launch_bounds__(NT, 4)
k_agg2(const int* __restrict__ nbd, const int* __restrict__ node_idx) {
    const int lane = threadIdx.x & 31, warp = threadIdx.x >> 5;
    const int slot = blockIdx.x * 8 + warp;
    const int gn = node_idx[slot];
    int nb = nbd[gn * DEG + lane];
    float4 acc = make_float4(-FLT_MAX, -FLT_MAX, -FLT_MAX, -FLT_MAX);
#pragma unroll 1
    for (int j = 0; j < DEG; ++j) {
        int nbj = __shfl_sync(0xffffffffu, nb, j);
        float4 m = *(const float4*)(g_M2 + nbj * WID + lane * 4);
        acc.x = fmaxf(acc.x, m.x); acc.y = fmaxf(acc.y, m.y);
        acc.z = fmaxf(acc.z, m.z); acc.w = fmaxf(acc.w, m.w);
    }
    *(float4*)(g_A2 + slot * WID + lane * 4) = acc;
}

// ---------------- layer 2 final: 256-K tensor combine + norm ----------------
#define L2F_SMEM ((2 * TM * APLD + 32 * WLD) * 8 + 2 * TM * 4 + TM * 4)
__global__ void __launch_bounds__(NT, 2)
k_l2f(const int* __restrict__ node_idx, const float* __restrict__ b_lin,
      float* __restrict__ out) {
    extern __shared__ float sm[];
    uint2* A1 = (uint2*)sm;
    uint2* A2 = A1 + TM * APLD;
    uint2* Ws = A2 + TM * APLD;
    float* ps = (float*)(Ws + 32 * WLD);
    int*   nid = (int*)(ps + 2 * TM);
    const int tid = threadIdx.x, lane = tid & 31, warp = tid >> 5;
    const int mw = warp >> 1, nw = warp & 1;
    const int g = lane >> 2, t4 = lane & 3;
    const int r0 = blockIdx.x * TM;

    if (tid < TM) nid[tid] = node_idx[r0 + tid];
    __syncthreads();

    for (int e = tid; e < TM * 64; e += NT) {
        int row = e >> 6, p = e & 63;
        uint32_t hi, lo;
        float2 f = *(const float2*)(g_H1 + nid[row] * WID + 2 * p);
        bfsplit2(f, hi, lo);
        A1[row * APLD + p] = make_uint2(hi, lo);
        float2 a = *(const float2*)(g_A2 + (r0 + row) * WID + 2 * p);
        bfsplit2(a, hi, lo);
        A2[row * APLD + p] = make_uint2(hi, lo);
    }
    // (tgemm's first stage-sync orders A1/A2 writes before reads)

    float C[8][4];
    zeroC(C);
    tgemm(A1, g_Wlh2, Ws, C, mw, nw, lane);
    tgemm(A2, g_Wla2, Ws, C, mw, nw, lane);      // accumulate second K-half

    float2 bl[8];
#pragma unroll
    for (int j = 0; j < 8; ++j)
        bl[j] = *(const float2*)(b_lin + nw * 64 + j * 8 + 2 * t4);
#pragma unroll
    for (int h = 0; h < 2; ++h) {
        int rloc = mw * 16 + g + 8 * h;
        float s = 0.f;
#pragma unroll
        for (int j = 0; j < 8; ++j) {
            float v0 = fmaxf(C[j][2 * h] + bl[j].x, 0.f);
            float v1 = fmaxf(C[j][2 * h + 1] + bl[j].y, 0.f);
            s += v0 * v0 + v1 * v1;
            C[j][2 * h] = v0; C[j][2 * h + 1] = v1;
        }
        s += __shfl_xor_sync(0xffffffffu, s, 1);
        s += __shfl_xor_sync(0xffffffffu, s, 2);
        if (t4 == 0) ps[nw * TM + rloc] = s;
    }
    __syncthreads();
#pragma unroll
    for (int h = 0; h < 2; ++h) {
        int rloc = mw * 16 + g + 8 * h;
        float t = ps[rloc] + ps[TM + rloc];
        float rinv = 1.0f / fmaxf(sqrtf(t), 1e-12f);
#pragma unroll
        for (int j = 0; j < 8; ++j) {
            float v0 = C[j][2 * h] * rinv;
            float v1 = C[j][2 * h + 1] * rinv;
            *(float2*)(out + (r0 + rloc) * WID + nw * 64 + j * 8 + 2 * t4) =
                make_float2(v0, v1);
        }
    }
}

// ---------------- launch ----------------
extern "C" void kernel_launch(void* const* d_in, const int* in_sizes, int n_in,
                              void* d_out, int out_size) {
    const int*   nbd      = (const int*)d_in[0];
    const int*   node_idx = (const int*)d_in[1];
    const float* feats    = (const float*)d_in[2];
    const float* W_agg    = (const float*)d_in[3];
    const float* b_agg    = (const float*)d_in[4];
    const float* W_lin    = (const float*)d_in[5];
    const float* b_lin    = (const float*)d_in[6];
    float* out = (float*)d_out;

    cudaFuncSetAttribute(k_batch, cudaFuncAttributeMaxDynamicSharedMemorySize, BATCH_SMEM);
    cudaFuncSetAttribute(k_main,  cudaFuncAttributeMaxDynamicSharedMemorySize, MAIN_SMEM);
    cudaFuncSetAttribute(k_l2f,   cudaFuncAttributeMaxDynamicSharedMemorySize, L2F_SMEM);

    k_init<<<(N_NODES + NT - 1) / NT, NT>>>(W_agg, W_lin);
    k_scatter<<<BATCH / NT, NT>>>(node_idx);
    k_batch<<<BATCH / TM, NT, BATCH_SMEM>>>(feats, b_agg);
    k_main<<<(N_NODES + TM - 1) / TM, NT, MAIN_SMEM>>>(nbd, b_agg, b_lin);
    k_agg2<<<BATCH / 8, NT>>>(nbd, node_idx);
    k_l2f<<<BATCH / TM, NT, L2F_SMEM>>>(node_idx, b_lin, out);
}